// round 16
// baseline (speedup 1.0000x reference)
#include <cuda_runtime.h>
#include <math.h>

#define NN 50000
#define NE 800000
#define NH 3
#define FMAX 192

#define SCAN_B 512
#define SCAN_NB 98            // 98*512 = 50176 >= NN+1

// ---------------- scratch (device globals) ----------------
__device__ float g_feat[NN * FMAX];    // projected features [N, H*Fo]
__device__ float g_el[NN * NH];
__device__ float g_er[NN * NH];
__device__ float g_rst[NN * FMAX];     // aggregation output
__device__ float g_h[NN * 64];         // inter-layer node features

__device__ int g_deg[SCAN_NB * SCAN_B];
__device__ int g_off[SCAN_NB * SCAN_B + 64];
__device__ int g_cur[NN];
__device__ int g_bsum[SCAN_NB + 8];
__device__ int g_csrc[NE];             // src node per CSR position

// ---------------- CSR build ----------------
__global__ void k_zero_deg() {
    int i = blockIdx.x * blockDim.x + threadIdx.x;
    if (i < SCAN_NB * SCAN_B) g_deg[i] = 0;
}

__global__ void k_count(const int* __restrict__ dst) {
    int e = blockIdx.x * blockDim.x + threadIdx.x;
    if (e < NE) atomicAdd(&g_deg[__ldg(dst + e)], 1);
}

__global__ void k_scan1() {
    __shared__ int s[SCAN_B];
    int t = threadIdx.x;
    int i = blockIdx.x * SCAN_B + t;
    int v = g_deg[i];
    s[t] = v;
    __syncthreads();
    for (int o = 1; o < SCAN_B; o <<= 1) {
        int x = (t >= o) ? s[t - o] : 0;
        __syncthreads();
        s[t] += x;
        __syncthreads();
    }
    g_off[i] = s[t] - v;               // exclusive within block
    if (t == SCAN_B - 1) g_bsum[blockIdx.x] = s[t];
}

__global__ void k_scan2() {             // 1 block of 128: scan 98 block sums
    __shared__ int s[128];
    int t = threadIdx.x;
    int v = (t < SCAN_NB) ? g_bsum[t] : 0;
    s[t] = v;
    __syncthreads();
    for (int o = 1; o < 128; o <<= 1) {
        int x = (t >= o) ? s[t - o] : 0;
        __syncthreads();
        s[t] += x;
        __syncthreads();
    }
    if (t < SCAN_NB) g_bsum[t] = s[t] - v;   // exclusive
}

__global__ void k_scan3() {
    int i = blockIdx.x * blockDim.x + threadIdx.x;
    if (i >= SCAN_NB * SCAN_B) return;
    int o = g_off[i] + g_bsum[i / SCAN_B];
    g_off[i] = o;
    if (i < NN) g_cur[i] = o;
}

__global__ void k_fill(const int* __restrict__ src, const int* __restrict__ dst) {
    int e = blockIdx.x * blockDim.x + threadIdx.x;
    if (e >= NE) return;
    int d = __ldg(dst + e);
    int pos = atomicAdd(&g_cur[d], 1);
    g_csrc[pos] = __ldg(src + e);
}

// ---------------- GEMMs ----------------
// scalar GEMM (ftot not multiple of 4; layer 3)
__global__ void k_gemm(const float* __restrict__ x, const float* __restrict__ W,
                       int fin, int ftot) {
    int i = blockIdx.x * blockDim.x + threadIdx.x;
    if (i >= NN * ftot) return;
    int n = i / ftot, c = i - n * ftot;
    const float* xr = x + n * fin;
    float acc = 0.f;
    #pragma unroll 4
    for (int k = 0; k < fin; k++) acc = fmaf(__ldg(xr + k), __ldg(W + k * ftot + c), acc);
    g_feat[i] = acc;
}

// float4 GEMM over output channels, scalar x loads (layer 1, fin=9)
__global__ void k_gemm_v4(const float* __restrict__ x, const float* __restrict__ W,
                          int fin, int ftot) {
    int nvec = ftot >> 2;
    int i = blockIdx.x * blockDim.x + threadIdx.x;
    if (i >= NN * nvec) return;
    int n = i / nvec, c4 = i - n * nvec;
    const float* xr = x + n * fin;
    float4 acc = {0.f, 0.f, 0.f, 0.f};
    #pragma unroll 4
    for (int k = 0; k < fin; k++) {
        float xv = __ldg(xr + k);
        float4 w = __ldg((const float4*)(W + k * ftot + c4 * 4));
        acc.x = fmaf(xv, w.x, acc.x);
        acc.y = fmaf(xv, w.y, acc.y);
        acc.z = fmaf(xv, w.z, acc.z);
        acc.w = fmaf(xv, w.w, acc.w);
    }
    ((float4*)g_feat)[i] = acc;
}

// float4 GEMM, float4 x loads too (fin%4==0 && ftot%4==0; layer 2)
__global__ void k_gemm_v4x4(const float* __restrict__ x, const float* __restrict__ W,
                            int fin, int ftot) {
    int nvec = ftot >> 2;
    int i = blockIdx.x * blockDim.x + threadIdx.x;
    if (i >= NN * nvec) return;
    int n = i / nvec, c4 = i - n * nvec;
    const float4* x4 = (const float4*)(x + n * fin);
    float4 acc = {0.f, 0.f, 0.f, 0.f};
    int k4n = fin >> 2;
    #pragma unroll 2
    for (int k4 = 0; k4 < k4n; k4++) {
        float4 xv = __ldg(x4 + k4);
        const float* Wb = W + (k4 << 2) * ftot + c4 * 4;
        float4 w0 = __ldg((const float4*)(Wb));
        float4 w1 = __ldg((const float4*)(Wb + ftot));
        float4 w2 = __ldg((const float4*)(Wb + 2 * ftot));
        float4 w3 = __ldg((const float4*)(Wb + 3 * ftot));
        acc.x = fmaf(xv.x, w0.x, acc.x); acc.y = fmaf(xv.x, w0.y, acc.y);
        acc.z = fmaf(xv.x, w0.z, acc.z); acc.w = fmaf(xv.x, w0.w, acc.w);
        acc.x = fmaf(xv.y, w1.x, acc.x); acc.y = fmaf(xv.y, w1.y, acc.y);
        acc.z = fmaf(xv.y, w1.z, acc.z); acc.w = fmaf(xv.y, w1.w, acc.w);
        acc.x = fmaf(xv.z, w2.x, acc.x); acc.y = fmaf(xv.z, w2.y, acc.y);
        acc.z = fmaf(xv.z, w2.z, acc.z); acc.w = fmaf(xv.z, w2.w, acc.w);
        acc.x = fmaf(xv.w, w3.x, acc.x); acc.y = fmaf(xv.w, w3.y, acc.y);
        acc.z = fmaf(xv.w, w3.z, acc.z); acc.w = fmaf(xv.w, w3.w, acc.w);
    }
    ((float4*)g_feat)[i] = acc;
}

__global__ void k_attn(const float* __restrict__ al, const float* __restrict__ ar, int fo) {
    int i = blockIdx.x * blockDim.x + threadIdx.x;
    if (i >= NN * NH) return;
    int n = i / NH, h = i - n * NH;
    const float* fr = g_feat + n * NH * fo + h * fo;
    float a = 0.f, b = 0.f;
    for (int f = 0; f < fo; f++) {
        float v = fr[f];
        a = fmaf(v, __ldg(al + h * fo + f), a);
        b = fmaf(v, __ldg(ar + h * fo + f), b);
    }
    g_el[i] = a;
    g_er[i] = b;
}

// ---------------- FUSED softmax + aggregation (Fo=64) ----------------
// warp per (dst, head); edges processed in chunks of 32:
//   phase A (lane-parallel): gather csrc + el, exp (no max shift — logits O(1))
//   phase B (lane = feature float2): broadcast a/s via shfl, gather feat, fma
// Accumulate unnormalized; single warp-reduced sum; scale at end.
__global__ void k_aggr64_f() {
    int gw = (blockIdx.x * blockDim.x + threadIdx.x) >> 5;
    if (gw >= NN * NH) return;
    int lane = threadIdx.x & 31;
    int d = gw / NH, h = gw - d * NH;
    int b0 = g_off[d], b1 = g_off[d + 1];
    float er = g_er[d * NH + h];
    const float2* featp = (const float2*)g_feat;
    int fvec = h * 32 + lane;
    float2 acc = {0.f, 0.f};
    float suml = 0.f;
    for (int p0 = b0; p0 < b1; p0 += 32) {
        int p = p0 + lane;
        int   sl = 0;
        float ex = 0.f;
        if (p < b1) {
            sl = g_csrc[p];
            float v = g_el[sl * NH + h] + er;
            v = v > 0.f ? v : 0.2f * v;
            ex = __expf(v);
        }
        suml += ex;
        int cnt = b1 - p0;
        if (cnt >= 32) {
            #pragma unroll 4
            for (int j = 0; j < 32; j++) {
                float a = __shfl_sync(0xffffffffu, ex, j);
                int   s = __shfl_sync(0xffffffffu, sl, j);
                float2 v = featp[s * 96 + fvec];
                acc.x = fmaf(a, v.x, acc.x);
                acc.y = fmaf(a, v.y, acc.y);
            }
        } else {
            for (int j = 0; j < cnt; j++) {
                float a = __shfl_sync(0xffffffffu, ex, j);
                int   s = __shfl_sync(0xffffffffu, sl, j);
                float2 v = featp[s * 96 + fvec];
                acc.x = fmaf(a, v.x, acc.x);
                acc.y = fmaf(a, v.y, acc.y);
            }
        }
    }
    #pragma unroll
    for (int o = 16; o > 0; o >>= 1)
        suml += __shfl_xor_sync(0xffffffffu, suml, o);
    float si = suml > 0.f ? 1.f / suml : 0.f;
    ((float2*)g_rst)[d * 96 + fvec] = make_float2(acc.x * si, acc.y * si);
}

// ---------------- FUSED softmax + aggregation (Fo=2) ----------------
// thread per (dst, head): single pass, accumulate sum + unnormalized acc
__global__ void k_aggr2_f() {
    int i = blockIdx.x * blockDim.x + threadIdx.x;
    if (i >= NN * NH) return;
    int d = i / NH, h = i - d * NH;
    int b0 = g_off[d], b1 = g_off[d + 1];
    float er = g_er[i];
    float sum = 0.f, a0 = 0.f, a1 = 0.f;
    for (int p = b0; p < b1; p++) {
        int s = g_csrc[p];
        float v = g_el[s * NH + h] + er;
        v = v > 0.f ? v : 0.2f * v;
        float e = __expf(v);
        sum += e;
        a0 = fmaf(e, g_feat[s * 6 + h * 2 + 0], a0);
        a1 = fmaf(e, g_feat[s * 6 + h * 2 + 1], a1);
    }
    float si = sum > 0.f ? 1.f / sum : 0.f;
    g_rst[d * 6 + h * 2 + 0] = a0 * si;
    g_rst[d * 6 + h * 2 + 1] = a1 * si;
}

// out[n,f] = sum_h (rst[n,h,f] + bias[h,f])
__global__ void k_final(const float* __restrict__ bias, float* __restrict__ out, int fo) {
    int i = blockIdx.x * blockDim.x + threadIdx.x;
    if (i >= NN * fo) return;
    int n = i / fo, f = i - n * fo;
    float acc = 0.f;
    #pragma unroll
    for (int h = 0; h < NH; h++)
        acc += g_rst[n * NH * fo + h * fo + f] + __ldg(bias + h * fo + f);
    out[i] = acc;
}

// ---------------- host side ----------------
static inline int cdiv(int a, int b) { return (a + b - 1) / b; }

static void run_layer(const float* x, const float* W, const float* al,
                      const float* ar, const float* bias,
                      int fin, int fo, float* out) {
    const int B = 256;
    int ftot = NH * fo;
    if ((fin & 3) == 0 && (ftot & 3) == 0)
        k_gemm_v4x4<<<cdiv(NN * (ftot >> 2), B), B>>>(x, W, fin, ftot);
    else if ((ftot & 3) == 0)
        k_gemm_v4<<<cdiv(NN * (ftot >> 2), B), B>>>(x, W, fin, ftot);
    else
        k_gemm<<<cdiv(NN * ftot, B), B>>>(x, W, fin, ftot);
    k_attn<<<cdiv(NN * NH, B), B>>>(al, ar, fo);
    if (fo == 64)
        k_aggr64_f<<<cdiv(NN * NH * 32, B), B>>>();
    else
        k_aggr2_f<<<cdiv(NN * NH, B), B>>>();
    k_final<<<cdiv(NN * fo, B), B>>>(bias, out, fo);
}

extern "C" void kernel_launch(void* const* d_in, const int* in_sizes, int n_in,
                              void* d_out, int out_size) {
    const float* feats = (const float*)d_in[0];
    const int*   src   = (const int*)d_in[1];
    const int*   dst   = (const int*)d_in[2];
    const float* W1  = (const float*)d_in[3];
    const float* al1 = (const float*)d_in[4];
    const float* ar1 = (const float*)d_in[5];
    const float* b1  = (const float*)d_in[6];
    const float* W2  = (const float*)d_in[7];
    const float* al2 = (const float*)d_in[8];
    const float* ar2 = (const float*)d_in[9];
    const float* b2  = (const float*)d_in[10];
    const float* W3  = (const float*)d_in[11];
    const float* al3 = (const float*)d_in[12];
    const float* ar3 = (const float*)d_in[13];
    const float* b3  = (const float*)d_in[14];

    const int B = 256;

    // Build CSR once (reused by all 3 layers)
    k_zero_deg<<<cdiv(SCAN_NB * SCAN_B, B), B>>>();
    k_count<<<cdiv(NE, B), B>>>(dst);
    k_scan1<<<SCAN_NB, SCAN_B>>>();
    k_scan2<<<1, 128>>>();
    k_scan3<<<cdiv(SCAN_NB * SCAN_B, B), B>>>();
    k_fill<<<cdiv(NE, B), B>>>(src, dst);

    float* hbuf = nullptr;
    cudaGetSymbolAddress((void**)&hbuf, g_h);

    run_layer(feats, W1, al1, ar1, b1, 9,  64, hbuf);
    run_layer(hbuf,  W2, al2, ar2, b2, 64, 64, hbuf);
    run_layer(hbuf,  W3, al3, ar3, b3, 64, 2,  (float*)d_out);
}